// round 1
// baseline (speedup 1.0000x reference)
#include <cuda_runtime.h>
#include <math.h>

#define NPEDS_MAX 8192
#define H 256
#define E 64
#define G4 1024   // 4*H
#define KTOT 320  // E + H
#define SEQ 30

// ---- device-global scratch (no allocations allowed) ----
__device__ float g_h[NPEDS_MAX * H];
__device__ float g_c[NPEDS_MAX * H];
__device__ float g_x[NPEDS_MAX * E];
__device__ float g_gates[NPEDS_MAX * G4];
__device__ float g_Wt[KTOT * G4];   // Wt[k][n] = concat(W_ih^T, W_hh^T)
__device__ float g_bias[G4];

__device__ __forceinline__ float sigm(float v) { return 1.f / (1.f + expf(-v)); }

// ---------------------------------------------------------------------------
// Init kernels (run every graph replay -> deterministic state reset)
// ---------------------------------------------------------------------------
__global__ void prep_weights(const float* __restrict__ W_ih, const float* __restrict__ W_hh,
                             const float* __restrict__ b_ih, const float* __restrict__ b_hh) {
  int idx = blockIdx.x * blockDim.x + threadIdx.x;
  if (idx < KTOT * G4) {
    int k = idx / G4, n = idx - k * G4;
    g_Wt[idx] = (k < E) ? W_ih[n * E + k] : W_hh[n * H + (k - E)];
  }
  if (idx < G4) g_bias[idx] = b_ih[idx] + b_hh[idx];
}

__global__ void init_state(const float* __restrict__ h0, const float* __restrict__ c0, int n) {
  int idx = blockIdx.x * blockDim.x + threadIdx.x;
  if (idx < n) { g_h[idx] = h0[idx]; g_c[idx] = c0[idx]; }
}

// embed(p) = leaky_relu( LN_2(p) @ emb_W^T + emb_b )
// LN over 2 elems: mu=(a+b)/2, d=(a-b)/2, var=d^2
__global__ void embed_init(const float* __restrict__ lpr,
                           const float* __restrict__ ln1_g, const float* __restrict__ ln1_b,
                           const float* __restrict__ emb_W, const float* __restrict__ emb_b,
                           int npeds) {
  int idx = blockIdx.x * blockDim.x + threadIdx.x;
  if (idx >= npeds * E) return;
  int ped = idx / E, j = idx - ped * E;
  float a = lpr[ped * 2 + 0], b = lpr[ped * 2 + 1];
  float d = 0.5f * (a - b);
  float inv = rsqrtf(d * d + 1e-5f);
  float na =  d * inv * ln1_g[0] + ln1_b[0];
  float nb = -d * inv * ln1_g[1] + ln1_b[1];
  float y = na * emb_W[j * 2 + 0] + nb * emb_W[j * 2 + 1] + emb_b[j];
  g_x[idx] = (y > 0.f) ? y : 0.01f * y;
}

// ---------------------------------------------------------------------------
// Per-step GEMM: g_gates[M=8192, N=1024] = [g_x | g_h][M,320] @ g_Wt[320,1024]
// BM=128, BN=64, BK=32, 256 threads, 8x4 per-thread microtile.
// ---------------------------------------------------------------------------
__global__ __launch_bounds__(256) void gates_gemm(int npeds) {
  __shared__ float As[32][132];  // transposed A tile, padded (16B-aligned rows)
  __shared__ float Bs[32][64];

  const int bm = blockIdx.y * 128;
  const int bn = blockIdx.x * 64;
  const int t = threadIdx.x;

  float acc[8][4];
#pragma unroll
  for (int i = 0; i < 8; ++i)
#pragma unroll
    for (int j = 0; j < 4; ++j) acc[i][j] = 0.f;

  const int tm = (t >> 4) << 3;  // 0..120
  const int tn = (t & 15) << 2;  // 0..60

  for (int kt = 0; kt < KTOT / 32; ++kt) {
    const int k0 = kt * 32;
    const float* src;
    int ldk, koff;
    if (k0 < E) { src = g_x; ldk = E; koff = k0; }
    else        { src = g_h; ldk = H; koff = k0 - E; }

    // A tile: 128 rows x 32 k, loaded as float4 along k, stored transposed
#pragma unroll
    for (int r = 0; r < 4; ++r) {
      int idx = t + r * 256;            // 0..1023
      int mm = idx >> 3;
      int kk4 = (idx & 7) << 2;
      const float4 v = *(const float4*)(src + (size_t)(bm + mm) * ldk + koff + kk4);
      As[kk4 + 0][mm] = v.x; As[kk4 + 1][mm] = v.y;
      As[kk4 + 2][mm] = v.z; As[kk4 + 3][mm] = v.w;
    }
    // B tile: 32 k x 64 n
#pragma unroll
    for (int r = 0; r < 2; ++r) {
      int idx = t + r * 256;            // 0..511
      int kk = idx >> 4;
      int nn4 = (idx & 15) << 2;
      *(float4*)&Bs[kk][nn4] = *(const float4*)(g_Wt + (size_t)(k0 + kk) * G4 + bn + nn4);
    }
    __syncthreads();

#pragma unroll
    for (int kk = 0; kk < 32; ++kk) {
      float a[8], b[4];
      *(float4*)&a[0] = *(const float4*)&As[kk][tm];
      *(float4*)&a[4] = *(const float4*)&As[kk][tm + 4];
      *(float4*)&b[0] = *(const float4*)&Bs[kk][tn];
#pragma unroll
      for (int i = 0; i < 8; ++i)
#pragma unroll
        for (int j = 0; j < 4; ++j)
          acc[i][j] = fmaf(a[i], b[j], acc[i][j]);
    }
    __syncthreads();
  }

#pragma unroll
  for (int i = 0; i < 8; ++i)
    *(float4*)(g_gates + (size_t)(bm + tm + i) * G4 + bn + tn) = *(float4*)&acc[i][0];
}

// ---------------------------------------------------------------------------
// Fused per-step tail: LSTM elementwise + LN2 + pos projection (rel out) +
// embed(rel) -> next x. One warp per ped; lane owns channels lane+32*j.
// ---------------------------------------------------------------------------
__global__ __launch_bounds__(256) void lstm_fused(
    const float* __restrict__ ln2_g, const float* __restrict__ ln2_b,
    const float* __restrict__ pos_W, const float* __restrict__ pos_b,
    const float* __restrict__ emb_W, const float* __restrict__ emb_b,
    const float* __restrict__ ln1_g, const float* __restrict__ ln1_b,
    float* __restrict__ rel_out, int npeds) {
  const int warp = threadIdx.x >> 5;
  const int lane = threadIdx.x & 31;
  const int ped = blockIdx.x * 8 + warp;
  if (ped >= npeds) return;

  const float* gp = g_gates + (size_t)ped * G4;
  float* cp = g_c + (size_t)ped * H;
  float* hp = g_h + (size_t)ped * H;

  float hn[8];
  float s = 0.f, ss = 0.f;
#pragma unroll
  for (int j = 0; j < 8; ++j) {
    const int ch = lane + j * 32;
    const float ig = gp[ch]           + g_bias[ch];
    const float fg = gp[256 + ch]     + g_bias[256 + ch];
    const float gg = gp[512 + ch]     + g_bias[512 + ch];
    const float og = gp[768 + ch]     + g_bias[768 + ch];
    const float cv = cp[ch];
    const float cn = sigm(fg) * cv + sigm(ig) * tanhf(gg);
    const float hv = sigm(og) * tanhf(cn);
    cp[ch] = cn;
    hp[ch] = hv;
    hn[j] = hv;
    s += hv;
    ss += hv * hv;
  }
#pragma unroll
  for (int o = 16; o > 0; o >>= 1) {
    s += __shfl_xor_sync(0xffffffffu, s, o);
    ss += __shfl_xor_sync(0xffffffffu, ss, o);
  }
  const float mu = s * (1.f / 256.f);
  const float var = ss * (1.f / 256.f) - mu * mu;
  const float rstd = rsqrtf(var + 1e-5f);

  float d0 = 0.f, d1 = 0.f;
#pragma unroll
  for (int j = 0; j < 8; ++j) {
    const int ch = lane + j * 32;
    const float nh = (hn[j] - mu) * rstd * ln2_g[ch] + ln2_b[ch];
    d0 += nh * pos_W[ch];
    d1 += nh * pos_W[256 + ch];
  }
#pragma unroll
  for (int o = 16; o > 0; o >>= 1) {
    d0 += __shfl_xor_sync(0xffffffffu, d0, o);
    d1 += __shfl_xor_sync(0xffffffffu, d1, o);
  }
  const float r0 = sigm(d0 + pos_b[0]);
  const float r1 = sigm(d1 + pos_b[1]);
  if (lane == 0) {
    rel_out[(size_t)ped * 2 + 0] = r0;
    rel_out[(size_t)ped * 2 + 1] = r1;
  }

  // embed(rel) -> next x  (LN over 2 elems)
  const float d = 0.5f * (r0 - r1);
  const float inv = rsqrtf(d * d + 1e-5f);
  const float na =  d * inv * ln1_g[0] + ln1_b[0];
  const float nb = -d * inv * ln1_g[1] + ln1_b[1];
  float* xp = g_x + (size_t)ped * E;
#pragma unroll
  for (int q = 0; q < 2; ++q) {
    const int j = lane * 2 + q;
    const float y = na * emb_W[j * 2 + 0] + nb * emb_W[j * 2 + 1] + emb_b[j];
    xp[j] = (y > 0.f) ? y : 0.01f * y;
  }
}

// ---------------------------------------------------------------------------
extern "C" void kernel_launch(void* const* d_in, const int* in_sizes, int n_in,
                              void* d_out, int out_size) {
  const float* last_pos_rel = (const float*)d_in[1];
  const float* h0   = (const float*)d_in[2];
  const float* c0   = (const float*)d_in[3];
  const float* W_ih = (const float*)d_in[4];
  const float* W_hh = (const float*)d_in[5];
  const float* b_ih = (const float*)d_in[6];
  const float* b_hh = (const float*)d_in[7];
  const float* emb_W = (const float*)d_in[8];
  const float* emb_b = (const float*)d_in[9];
  const float* ln1_g = (const float*)d_in[10];
  const float* ln1_b = (const float*)d_in[11];
  const float* pos_W = (const float*)d_in[12];
  const float* pos_b = (const float*)d_in[13];
  const float* ln2_g = (const float*)d_in[14];
  const float* ln2_b = (const float*)d_in[15];
  float* out = (float*)d_out;

  const int npeds = in_sizes[0] / 2;  // 8192

  prep_weights<<<(KTOT * G4 + 255) / 256, 256>>>(W_ih, W_hh, b_ih, b_hh);
  init_state<<<(npeds * H + 255) / 256, 256>>>(h0, c0, npeds * H);
  embed_init<<<(npeds * E + 255) / 256, 256>>>(last_pos_rel, ln1_g, ln1_b, emb_W, emb_b, npeds);

  dim3 ggrid(G4 / 64, npeds / 128);
  for (int s = 0; s < SEQ; ++s) {
    gates_gemm<<<ggrid, 256>>>(npeds);
    lstm_fused<<<npeds / 8, 256>>>(ln2_g, ln2_b, pos_W, pos_b, emb_W, emb_b,
                                   ln1_g, ln1_b, out + (size_t)s * npeds * 2, npeds);
  }
}

// round 2
// speedup vs baseline: 2.3212x; 2.3212x over previous
#include <cuda_runtime.h>
#include <math.h>
#include <stdint.h>

#define NPEDS_MAX 8192
#define H 256
#define E 64
#define G4 1024   // 4*H
#define KTOT 320  // E + H
#define SEQ 30

// ---- device-global scratch (no allocations allowed) ----
__device__ float g_h[NPEDS_MAX * H];
__device__ float g_c[NPEDS_MAX * H];
__device__ float g_x[NPEDS_MAX * E];
__device__ float g_gates[NPEDS_MAX * G4];
__device__ uint32_t g_Wt[KTOT * G4];   // tf32 bits: Wt[k][n] = concat(W_ih^T, W_hh^T)
__device__ float g_bias[G4];

__device__ __forceinline__ float sigm(float v) { return 1.f / (1.f + expf(-v)); }

__device__ __forceinline__ uint32_t f2tf(float f) {
  uint32_t u;
  asm("cvt.rna.tf32.f32 %0, %1;" : "=r"(u) : "f"(f));
  return u;
}

// ---------------------------------------------------------------------------
// Init kernels (run every graph replay -> deterministic state reset)
// ---------------------------------------------------------------------------
__global__ void prep_weights(const float* __restrict__ W_ih, const float* __restrict__ W_hh,
                             const float* __restrict__ b_ih, const float* __restrict__ b_hh) {
  int idx = blockIdx.x * blockDim.x + threadIdx.x;
  if (idx < KTOT * G4) {
    int k = idx / G4, n = idx - k * G4;
    float w = (k < E) ? W_ih[n * E + k] : W_hh[n * H + (k - E)];
    g_Wt[idx] = f2tf(w);
  }
  if (idx < G4) g_bias[idx] = b_ih[idx] + b_hh[idx];
}

__global__ void init_state(const float* __restrict__ h0, const float* __restrict__ c0, int n) {
  int idx = blockIdx.x * blockDim.x + threadIdx.x;
  if (idx < n) { g_h[idx] = h0[idx]; g_c[idx] = c0[idx]; }
}

// embed(p) = leaky_relu( LN_2(p) @ emb_W^T + emb_b )
__global__ void embed_init(const float* __restrict__ lpr,
                           const float* __restrict__ ln1_g, const float* __restrict__ ln1_b,
                           const float* __restrict__ emb_W, const float* __restrict__ emb_b,
                           int npeds) {
  int idx = blockIdx.x * blockDim.x + threadIdx.x;
  if (idx >= npeds * E) return;
  int ped = idx / E, j = idx - ped * E;
  float a = lpr[ped * 2 + 0], b = lpr[ped * 2 + 1];
  float d = 0.5f * (a - b);
  float inv = rsqrtf(d * d + 1e-5f);
  float na =  d * inv * ln1_g[0] + ln1_b[0];
  float nb = -d * inv * ln1_g[1] + ln1_b[1];
  float y = na * emb_W[j * 2 + 0] + nb * emb_W[j * 2 + 1] + emb_b[j];
  g_x[idx] = (y > 0.f) ? y : 0.01f * y;
}

// ---------------------------------------------------------------------------
// Per-step GEMM (TF32 tensor core):
//   g_gates[M=8192, N=1024] = [g_x | g_h][M,320] @ g_Wt[320,1024]
// BM=128, BN=128, BK=32. 256 threads = 8 warps (2m x 4n), warp tile 64x32.
// mma.sync.m16n8k8.tf32, fp32 accumulate.
// ---------------------------------------------------------------------------
__global__ __launch_bounds__(256, 2) void gates_gemm(int npeds) {
  __shared__ uint32_t As[128][36];   // [m][k], pad -> conflict-free a-frag LDS
  __shared__ uint32_t Bs[32][136];   // [k][n], pad 8 -> conflict-free b-frag LDS

  const int bm = blockIdx.y * 128;
  const int bn = blockIdx.x * 128;
  const int t = threadIdx.x;
  const int warp = t >> 5;
  const int lane = t & 31;
  const int wm = (warp >> 2) * 64;   // warp row offset in tile
  const int wn = (warp & 3) * 32;    // warp col offset in tile
  const int lr = lane >> 2;          // lane row group 0..7
  const int lc = lane & 3;           // lane col group 0..3

  float acc[4][4][4];                // [mt][nt][c0..c3]
#pragma unroll
  for (int i = 0; i < 4; ++i)
#pragma unroll
    for (int j = 0; j < 4; ++j)
#pragma unroll
      for (int q = 0; q < 4; ++q) acc[i][j][q] = 0.f;

  for (int kt = 0; kt < KTOT / 32; ++kt) {
    const int k0 = kt * 32;
    const float* src;
    int ldk, koff;
    if (k0 < E) { src = g_x; ldk = E; koff = k0; }
    else        { src = g_h; ldk = H; koff = k0 - E; }

    // ---- A tile: 128 rows x 32 k ----
#pragma unroll
    for (int r = 0; r < 4; ++r) {
      int idx = t + r * 256;             // 0..1023
      int mm = idx >> 3;
      int kk4 = (idx & 7) << 2;
      const float4 v = *(const float4*)(src + (size_t)(bm + mm) * ldk + koff + kk4);
      uint4 u = make_uint4(f2tf(v.x), f2tf(v.y), f2tf(v.z), f2tf(v.w));
      *(uint4*)&As[mm][kk4] = u;
    }
    // ---- B tile: 32 k x 128 n (already tf32 bits) ----
#pragma unroll
    for (int r = 0; r < 4; ++r) {
      int idx = t + r * 256;             // 0..1023
      int kk = idx >> 5;
      int nn4 = (idx & 31) << 2;
      uint4 u = *(const uint4*)(g_Wt + (size_t)(k0 + kk) * G4 + bn + nn4);
      *(uint4*)&Bs[kk][nn4] = u;
    }
    __syncthreads();

#pragma unroll
    for (int ks = 0; ks < 4; ++ks) {
      const int kb = ks * 8;
      uint32_t a[4][4], b[4][2];
#pragma unroll
      for (int mt = 0; mt < 4; ++mt) {
        const int ar = wm + mt * 16 + lr;
        a[mt][0] = As[ar][kb + lc];
        a[mt][1] = As[ar + 8][kb + lc];
        a[mt][2] = As[ar][kb + lc + 4];
        a[mt][3] = As[ar + 8][kb + lc + 4];
      }
#pragma unroll
      for (int nt = 0; nt < 4; ++nt) {
        const int bc = wn + nt * 8 + lr;
        b[nt][0] = Bs[kb + lc][bc];
        b[nt][1] = Bs[kb + lc + 4][bc];
      }
#pragma unroll
      for (int mt = 0; mt < 4; ++mt)
#pragma unroll
        for (int nt = 0; nt < 4; ++nt) {
          asm volatile(
            "mma.sync.aligned.m16n8k8.row.col.f32.tf32.tf32.f32 "
            "{%0,%1,%2,%3}, {%4,%5,%6,%7}, {%8,%9}, {%0,%1,%2,%3};"
            : "+f"(acc[mt][nt][0]), "+f"(acc[mt][nt][1]),
              "+f"(acc[mt][nt][2]), "+f"(acc[mt][nt][3])
            : "r"(a[mt][0]), "r"(a[mt][1]), "r"(a[mt][2]), "r"(a[mt][3]),
              "r"(b[nt][0]), "r"(b[nt][1]));
        }
    }
    __syncthreads();
  }

  // ---- epilogue: write fp32 gates ----
#pragma unroll
  for (int mt = 0; mt < 4; ++mt) {
    const int row = bm + wm + mt * 16 + lr;
#pragma unroll
    for (int nt = 0; nt < 4; ++nt) {
      const int col = bn + wn + nt * 8 + lc * 2;
      *(float2*)(g_gates + (size_t)row * G4 + col) =
          make_float2(acc[mt][nt][0], acc[mt][nt][1]);
      *(float2*)(g_gates + (size_t)(row + 8) * G4 + col) =
          make_float2(acc[mt][nt][2], acc[mt][nt][3]);
    }
  }
}

// ---------------------------------------------------------------------------
// Fused per-step tail: LSTM elementwise + LN2 + pos projection (rel out) +
// embed(rel) -> next x. One warp per ped.
// ---------------------------------------------------------------------------
__global__ __launch_bounds__(256) void lstm_fused(
    const float* __restrict__ ln2_g, const float* __restrict__ ln2_b,
    const float* __restrict__ pos_W, const float* __restrict__ pos_b,
    const float* __restrict__ emb_W, const float* __restrict__ emb_b,
    const float* __restrict__ ln1_g, const float* __restrict__ ln1_b,
    float* __restrict__ rel_out, int npeds) {
  const int warp = threadIdx.x >> 5;
  const int lane = threadIdx.x & 31;
  const int ped = blockIdx.x * 8 + warp;
  if (ped >= npeds) return;

  const float* gp = g_gates + (size_t)ped * G4;
  float* cp = g_c + (size_t)ped * H;
  float* hp = g_h + (size_t)ped * H;

  float hn[8];
  float s = 0.f, ss = 0.f;
#pragma unroll
  for (int j = 0; j < 8; ++j) {
    const int ch = lane + j * 32;
    const float ig = gp[ch]           + g_bias[ch];
    const float fg = gp[256 + ch]     + g_bias[256 + ch];
    const float gg = gp[512 + ch]     + g_bias[512 + ch];
    const float og = gp[768 + ch]     + g_bias[768 + ch];
    const float cv = cp[ch];
    const float cn = sigm(fg) * cv + sigm(ig) * tanhf(gg);
    const float hv = sigm(og) * tanhf(cn);
    cp[ch] = cn;
    hp[ch] = hv;
    hn[j] = hv;
    s += hv;
    ss += hv * hv;
  }
#pragma unroll
  for (int o = 16; o > 0; o >>= 1) {
    s += __shfl_xor_sync(0xffffffffu, s, o);
    ss += __shfl_xor_sync(0xffffffffu, ss, o);
  }
  const float mu = s * (1.f / 256.f);
  const float var = ss * (1.f / 256.f) - mu * mu;
  const float rstd = rsqrtf(var + 1e-5f);

  float d0 = 0.f, d1 = 0.f;
#pragma unroll
  for (int j = 0; j < 8; ++j) {
    const int ch = lane + j * 32;
    const float nh = (hn[j] - mu) * rstd * ln2_g[ch] + ln2_b[ch];
    d0 += nh * pos_W[ch];
    d1 += nh * pos_W[256 + ch];
  }
#pragma unroll
  for (int o = 16; o > 0; o >>= 1) {
    d0 += __shfl_xor_sync(0xffffffffu, d0, o);
    d1 += __shfl_xor_sync(0xffffffffu, d1, o);
  }
  const float r0 = sigm(d0 + pos_b[0]);
  const float r1 = sigm(d1 + pos_b[1]);
  if (lane == 0) {
    rel_out[(size_t)ped * 2 + 0] = r0;
    rel_out[(size_t)ped * 2 + 1] = r1;
  }

  // embed(rel) -> next x  (LN over 2 elems)
  const float d = 0.5f * (r0 - r1);
  const float inv = rsqrtf(d * d + 1e-5f);
  const float na =  d * inv * ln1_g[0] + ln1_b[0];
  const float nb = -d * inv * ln1_g[1] + ln1_b[1];
  float* xp = g_x + (size_t)ped * E;
#pragma unroll
  for (int q = 0; q < 2; ++q) {
    const int j = lane * 2 + q;
    const float y = na * emb_W[j * 2 + 0] + nb * emb_W[j * 2 + 1] + emb_b[j];
    xp[j] = (y > 0.f) ? y : 0.01f * y;
  }
}

// ---------------------------------------------------------------------------
extern "C" void kernel_launch(void* const* d_in, const int* in_sizes, int n_in,
                              void* d_out, int out_size) {
  const float* last_pos_rel = (const float*)d_in[1];
  const float* h0   = (const float*)d_in[2];
  const float* c0   = (const float*)d_in[3];
  const float* W_ih = (const float*)d_in[4];
  const float* W_hh = (const float*)d_in[5];
  const float* b_ih = (const float*)d_in[6];
  const float* b_hh = (const float*)d_in[7];
  const float* emb_W = (const float*)d_in[8];
  const float* emb_b = (const float*)d_in[9];
  const float* ln1_g = (const float*)d_in[10];
  const float* ln1_b = (const float*)d_in[11];
  const float* pos_W = (const float*)d_in[12];
  const float* pos_b = (const float*)d_in[13];
  const float* ln2_g = (const float*)d_in[14];
  const float* ln2_b = (const float*)d_in[15];
  float* out = (float*)d_out;

  const int npeds = in_sizes[0] / 2;  // 8192

  prep_weights<<<(KTOT * G4 + 255) / 256, 256>>>(W_ih, W_hh, b_ih, b_hh);
  init_state<<<(npeds * H + 255) / 256, 256>>>(h0, c0, npeds * H);
  embed_init<<<(npeds * E + 255) / 256, 256>>>(last_pos_rel, ln1_g, ln1_b, emb_W, emb_b, npeds);

  dim3 ggrid(G4 / 128, npeds / 128);
  for (int s = 0; s < SEQ; ++s) {
    gates_gemm<<<ggrid, 256>>>(npeds);
    lstm_fused<<<npeds / 8, 256>>>(ln2_g, ln2_b, pos_W, pos_b, emb_W, emb_b,
                                   ln1_g, ln1_b, out + (size_t)s * npeds * 2, npeds);
  }
}

// round 3
// speedup vs baseline: 3.2950x; 1.4195x over previous
#include <cuda_runtime.h>
#include <cuda_bf16.h>
#include <math.h>
#include <stdint.h>

#define NPEDS_MAX 8192
#define H 256
#define E 64
#define G4 1024   // 4*H
#define KTOT 320  // E + H
#define SEQ 30
#define KT_TILES 10  // KTOT/32

// ---- device-global scratch (no allocations allowed) ----
__device__ __align__(16) __nv_bfloat16 g_h[NPEDS_MAX * H];
__device__ float g_c[NPEDS_MAX * H];
__device__ __align__(16) __nv_bfloat16 g_x[NPEDS_MAX * E];
__device__ float g_gates[NPEDS_MAX * G4];
__device__ __align__(16) __nv_bfloat16 g_Wn[G4 * KTOT];  // [n][k] bf16
__device__ float g_bias[G4];

__device__ __forceinline__ float sigm(float v) { return 1.f / (1.f + expf(-v)); }

// ---------------------------------------------------------------------------
// Init kernels (run every graph replay -> deterministic state reset)
// ---------------------------------------------------------------------------
__global__ void prep_weights(const float* __restrict__ W_ih, const float* __restrict__ W_hh,
                             const float* __restrict__ b_ih, const float* __restrict__ b_hh) {
  int idx = blockIdx.x * blockDim.x + threadIdx.x;
  if (idx < G4 * KTOT) {
    int n = idx / KTOT, k = idx - n * KTOT;
    float w = (k < E) ? W_ih[n * E + k] : W_hh[n * H + (k - E)];
    g_Wn[idx] = __float2bfloat16(w);
  }
  if (idx < G4) g_bias[idx] = b_ih[idx] + b_hh[idx];
}

__global__ void init_state(const float* __restrict__ h0, const float* __restrict__ c0, int n) {
  int idx = blockIdx.x * blockDim.x + threadIdx.x;
  if (idx < n) { g_h[idx] = __float2bfloat16(h0[idx]); g_c[idx] = c0[idx]; }
}

// embed(p) = leaky_relu( LN_2(p) @ emb_W^T + emb_b )
__global__ void embed_init(const float* __restrict__ lpr,
                           const float* __restrict__ ln1_g, const float* __restrict__ ln1_b,
                           const float* __restrict__ emb_W, const float* __restrict__ emb_b,
                           int npeds) {
  int idx = blockIdx.x * blockDim.x + threadIdx.x;
  if (idx >= npeds * E) return;
  int ped = idx / E, j = idx - ped * E;
  float a = lpr[ped * 2 + 0], b = lpr[ped * 2 + 1];
  float d = 0.5f * (a - b);
  float inv = rsqrtf(d * d + 1e-5f);
  float na =  d * inv * ln1_g[0] + ln1_b[0];
  float nb = -d * inv * ln1_g[1] + ln1_b[1];
  float y = na * emb_W[j * 2 + 0] + nb * emb_W[j * 2 + 1] + emb_b[j];
  g_x[idx] = __float2bfloat16((y > 0.f) ? y : 0.01f * y);
}

// ---------------------------------------------------------------------------
// Per-step GEMM (bf16 tensor core, cp.async double-buffered):
//   g_gates[M=8192, N=1024] = [g_x | g_h][M,320] @ W^T  (weights as [n][k])
// BM=128, BN=128, BK=32. 8 warps (2m x 4n), warp tile 64x32.
// mma.sync.m16n8k16.row.col.f32.bf16.bf16.f32
// ---------------------------------------------------------------------------
__global__ __launch_bounds__(256, 2) void gates_gemm(int npeds) {
  // rows padded to 20 uint32 (=40 bf16 =80B): conflict-free frag LDS,
  // 16B-aligned rows for cp.async
  __shared__ __align__(16) uint32_t As[2][128][20];  // [m][k-pairs]
  __shared__ __align__(16) uint32_t Bs[2][128][20];  // [n][k-pairs]

  const int bm = blockIdx.y * 128;
  const int bn = blockIdx.x * 128;
  const int t = threadIdx.x;
  const int warp = t >> 5;
  const int lane = t & 31;
  const int wm = (warp >> 2) * 64;
  const int wn = (warp & 3) * 32;
  const int gr = lane >> 2;   // 0..7
  const int lc = lane & 3;    // 0..3

  float acc[4][4][4];
#pragma unroll
  for (int i = 0; i < 4; ++i)
#pragma unroll
    for (int j = 0; j < 4; ++j)
#pragma unroll
      for (int q = 0; q < 4; ++q) acc[i][j][q] = 0.f;

  // thread -> 16B chunk mapping for tile loads (128 rows x 4 chunks = 512)
  const int mm0 = t >> 2;          // rows for r=0 pass: 0..63
  const int c4 = t & 3;            // chunk 0..3 (8 bf16 each)

  auto load_tile = [&](int kt, int buf) {
    const int k0 = kt * 32;
    const __nv_bfloat16* srcA;
    int ldk, koff;
    if (k0 < E) { srcA = g_x; ldk = E; koff = k0; }
    else        { srcA = g_h; ldk = H; koff = k0 - E; }
#pragma unroll
    for (int r = 0; r < 2; ++r) {
      const int mm = mm0 + r * 64;
      const void* gA = srcA + (size_t)(bm + mm) * ldk + koff + c4 * 8;
      uint32_t dA = (uint32_t)__cvta_generic_to_shared(&As[buf][mm][c4 * 4]);
      asm volatile("cp.async.cg.shared.global [%0], [%1], 16;\n" :: "r"(dA), "l"(gA));
      const void* gB = g_Wn + (size_t)(bn + mm) * KTOT + k0 + c4 * 8;
      uint32_t dB = (uint32_t)__cvta_generic_to_shared(&Bs[buf][mm][c4 * 4]);
      asm volatile("cp.async.cg.shared.global [%0], [%1], 16;\n" :: "r"(dB), "l"(gB));
    }
    asm volatile("cp.async.commit_group;\n");
  };

  load_tile(0, 0);

  for (int kt = 0; kt < KT_TILES; ++kt) {
    asm volatile("cp.async.wait_group 0;\n");
    __syncthreads();
    if (kt + 1 < KT_TILES) load_tile(kt + 1, (kt + 1) & 1);
    const int buf = kt & 1;

#pragma unroll
    for (int ks = 0; ks < 2; ++ks) {
      const int kb = ks * 8;   // uint32 (bf16-pair) column base
      uint32_t a[4][4], b[4][2];
#pragma unroll
      for (int mt = 0; mt < 4; ++mt) {
        const int ar = wm + mt * 16 + gr;
        a[mt][0] = As[buf][ar][kb + lc];
        a[mt][1] = As[buf][ar + 8][kb + lc];
        a[mt][2] = As[buf][ar][kb + lc + 4];
        a[mt][3] = As[buf][ar + 8][kb + lc + 4];
      }
#pragma unroll
      for (int nt = 0; nt < 4; ++nt) {
        const int br = wn + nt * 8 + gr;
        b[nt][0] = Bs[buf][br][kb + lc];
        b[nt][1] = Bs[buf][br][kb + lc + 4];
      }
#pragma unroll
      for (int mt = 0; mt < 4; ++mt)
#pragma unroll
        for (int nt = 0; nt < 4; ++nt) {
          asm volatile(
            "mma.sync.aligned.m16n8k16.row.col.f32.bf16.bf16.f32 "
            "{%0,%1,%2,%3}, {%4,%5,%6,%7}, {%8,%9}, {%0,%1,%2,%3};"
            : "+f"(acc[mt][nt][0]), "+f"(acc[mt][nt][1]),
              "+f"(acc[mt][nt][2]), "+f"(acc[mt][nt][3])
            : "r"(a[mt][0]), "r"(a[mt][1]), "r"(a[mt][2]), "r"(a[mt][3]),
              "r"(b[nt][0]), "r"(b[nt][1]));
        }
    }
  }

  // ---- epilogue: write fp32 gates ----
#pragma unroll
  for (int mt = 0; mt < 4; ++mt) {
    const int row = bm + wm + mt * 16 + gr;
#pragma unroll
    for (int nt = 0; nt < 4; ++nt) {
      const int col = bn + wn + nt * 8 + lc * 2;
      *(float2*)(g_gates + (size_t)row * G4 + col) =
          make_float2(acc[mt][nt][0], acc[mt][nt][1]);
      *(float2*)(g_gates + (size_t)(row + 8) * G4 + col) =
          make_float2(acc[mt][nt][2], acc[mt][nt][3]);
    }
  }
}

// ---------------------------------------------------------------------------
// Fused per-step tail: LSTM elementwise + LN2 + pos projection (rel out) +
// embed(rel) -> next x. One warp per ped.
// ---------------------------------------------------------------------------
__global__ __launch_bounds__(256) void lstm_fused(
    const float* __restrict__ ln2_g, const float* __restrict__ ln2_b,
    const float* __restrict__ pos_W, const float* __restrict__ pos_b,
    const float* __restrict__ emb_W, const float* __restrict__ emb_b,
    const float* __restrict__ ln1_g, const float* __restrict__ ln1_b,
    float* __restrict__ rel_out, int npeds) {
  const int warp = threadIdx.x >> 5;
  const int lane = threadIdx.x & 31;
  const int ped = blockIdx.x * 8 + warp;
  if (ped >= npeds) return;

  const float* gp = g_gates + (size_t)ped * G4;
  float* cp = g_c + (size_t)ped * H;
  __nv_bfloat16* hp = g_h + (size_t)ped * H;

  float hn[8];
  float s = 0.f, ss = 0.f;
#pragma unroll
  for (int j = 0; j < 8; ++j) {
    const int ch = lane + j * 32;
    const float ig = gp[ch]           + g_bias[ch];
    const float fg = gp[256 + ch]     + g_bias[256 + ch];
    const float gg = gp[512 + ch]     + g_bias[512 + ch];
    const float og = gp[768 + ch]     + g_bias[768 + ch];
    const float cv = cp[ch];
    const float cn = sigm(fg) * cv + sigm(ig) * tanhf(gg);
    const float hv = sigm(og) * tanhf(cn);
    cp[ch] = cn;
    hp[ch] = __float2bfloat16(hv);
    hn[j] = hv;
    s += hv;
    ss += hv * hv;
  }
#pragma unroll
  for (int o = 16; o > 0; o >>= 1) {
    s += __shfl_xor_sync(0xffffffffu, s, o);
    ss += __shfl_xor_sync(0xffffffffu, ss, o);
  }
  const float mu = s * (1.f / 256.f);
  const float var = ss * (1.f / 256.f) - mu * mu;
  const float rstd = rsqrtf(var + 1e-5f);

  float d0 = 0.f, d1 = 0.f;
#pragma unroll
  for (int j = 0; j < 8; ++j) {
    const int ch = lane + j * 32;
    const float nh = (hn[j] - mu) * rstd * ln2_g[ch] + ln2_b[ch];
    d0 += nh * pos_W[ch];
    d1 += nh * pos_W[256 + ch];
  }
#pragma unroll
  for (int o = 16; o > 0; o >>= 1) {
    d0 += __shfl_xor_sync(0xffffffffu, d0, o);
    d1 += __shfl_xor_sync(0xffffffffu, d1, o);
  }
  const float r0 = sigm(d0 + pos_b[0]);
  const float r1 = sigm(d1 + pos_b[1]);
  if (lane == 0) {
    rel_out[(size_t)ped * 2 + 0] = r0;
    rel_out[(size_t)ped * 2 + 1] = r1;
  }

  // embed(rel) -> next x  (LN over 2 elems)
  const float d = 0.5f * (r0 - r1);
  const float inv = rsqrtf(d * d + 1e-5f);
  const float na =  d * inv * ln1_g[0] + ln1_b[0];
  const float nb = -d * inv * ln1_g[1] + ln1_b[1];
  __nv_bfloat16* xp = g_x + (size_t)ped * E;
#pragma unroll
  for (int q = 0; q < 2; ++q) {
    const int j = lane * 2 + q;
    const float y = na * emb_W[j * 2 + 0] + nb * emb_W[j * 2 + 1] + emb_b[j];
    xp[j] = __float2bfloat16((y > 0.f) ? y : 0.01f * y);
  }
}

// ---------------------------------------------------------------------------
extern "C" void kernel_launch(void* const* d_in, const int* in_sizes, int n_in,
                              void* d_out, int out_size) {
  const float* last_pos_rel = (const float*)d_in[1];
  const float* h0   = (const float*)d_in[2];
  const float* c0   = (const float*)d_in[3];
  const float* W_ih = (const float*)d_in[4];
  const float* W_hh = (const float*)d_in[5];
  const float* b_ih = (const float*)d_in[6];
  const float* b_hh = (const float*)d_in[7];
  const float* emb_W = (const float*)d_in[8];
  const float* emb_b = (const float*)d_in[9];
  const float* ln1_g = (const float*)d_in[10];
  const float* ln1_b = (const float*)d_in[11];
  const float* pos_W = (const float*)d_in[12];
  const float* pos_b = (const float*)d_in[13];
  const float* ln2_g = (const float*)d_in[14];
  const float* ln2_b = (const float*)d_in[15];
  float* out = (float*)d_out;

  const int npeds = in_sizes[0] / 2;  // 8192

  prep_weights<<<(G4 * KTOT + 255) / 256, 256>>>(W_ih, W_hh, b_ih, b_hh);
  init_state<<<(npeds * H + 255) / 256, 256>>>(h0, c0, npeds * H);
  embed_init<<<(npeds * E + 255) / 256, 256>>>(last_pos_rel, ln1_g, ln1_b, emb_W, emb_b, npeds);

  dim3 ggrid(G4 / 128, npeds / 128);
  for (int s = 0; s < SEQ; ++s) {
    gates_gemm<<<ggrid, 256>>>(npeds);
    lstm_fused<<<npeds / 8, 256>>>(ln2_g, ln2_b, pos_W, pos_b, emb_W, emb_b,
                                   ln1_g, ln1_b, out + (size_t)s * npeds * 2, npeds);
  }
}